// round 2
// baseline (speedup 1.0000x reference)
#include <cuda_runtime.h>
#include <cuda_bf16.h>

#define MAX_ROWS 8192
__device__ double g_row_loss[MAX_ROWS];

// One block per row: sum exp(30*x) over the row, then per-row scalar epilogue.
__global__ void __launch_bounds__(256) cosarc_row_kernel(
    const float* __restrict__ preds,
    const int* __restrict__ labels,   // JAX x64 disabled -> labels are int32
    int V)
{
    const int row = blockIdx.x;
    const float* rp = preds + (size_t)row * (size_t)V;
    const float4* p4 = reinterpret_cast<const float4*>(rp);
    const int n4 = V >> 2;

    // exp(30*x) = exp2(x * 30*log2(e))
    const float C = 30.0f * 1.4426950408889634f;

    float s = 0.0f;
    for (int i = threadIdx.x; i < n4; i += blockDim.x) {
        float4 v = __ldg(&p4[i]);
        s += exp2f(v.x * C);
        s += exp2f(v.y * C);
        s += exp2f(v.z * C);
        s += exp2f(v.w * C);
    }
    // Tail (V not multiple of 4) — not hit for V=32000, kept for safety.
    for (int i = (n4 << 2) + threadIdx.x; i < V; i += blockDim.x) {
        s += exp2f(rp[i] * C);
    }

    // Warp reduce
    #pragma unroll
    for (int o = 16; o > 0; o >>= 1)
        s += __shfl_xor_sync(0xffffffffu, s, o);

    __shared__ float warpsum[8];
    const int wid = threadIdx.x >> 5;
    const int lid = threadIdx.x & 31;
    if (lid == 0) warpsum[wid] = s;
    __syncthreads();

    if (threadIdx.x == 0) {
        float tot = 0.0f;
        #pragma unroll
        for (int w = 0; w < 8; w++) tot += warpsum[w];

        int lab = labels[row];
        // Defensive clamp: a bad label degrades to wrong answer, not a crash.
        if (lab < 0) lab = 0;
        if (lab >= V) lab = V - 1;
        const float target = rp[lab];

        // Remove the target-class term exactly as it was added (fp32 exp2f).
        double sum_others = (double)tot - (double)exp2f(target * C);

        const double EPS = 1e-12;
        const double PI  = 3.14159265358979323846;
        double t = (double)target;
        t = fmin(fmax(t, -1.0 + EPS), 1.0 - EPS);
        double theta = acos(t);
        theta = fmin(fmax(theta, EPS), PI - EPS);
        double numerator = 30.0 * (cos(theta + 0.5) - 0.35);
        double denominator = exp(numerator) + sum_others;
        g_row_loss[row] = numerator - log(denominator);
    }
}

// Single-block deterministic final reduction: out = -mean(row_loss)
__global__ void __launch_bounds__(256) cosarc_final_kernel(float* __restrict__ out, int B)
{
    double s = 0.0;
    for (int i = threadIdx.x; i < B; i += blockDim.x)
        s += g_row_loss[i];

    #pragma unroll
    for (int o = 16; o > 0; o >>= 1)
        s += __shfl_xor_sync(0xffffffffu, s, o);

    __shared__ double warpsum[8];
    const int wid = threadIdx.x >> 5;
    const int lid = threadIdx.x & 31;
    if (lid == 0) warpsum[wid] = s;
    __syncthreads();

    if (threadIdx.x == 0) {
        double tot = 0.0;
        #pragma unroll
        for (int w = 0; w < 8; w++) tot += warpsum[w];
        out[0] = (float)(-tot / (double)B);
    }
}

extern "C" void kernel_launch(void* const* d_in, const int* in_sizes, int n_in,
                              void* d_out, int out_size)
{
    const float* preds  = (const float*)d_in[0];
    const int*   labels = (const int*)d_in[1];

    const int B = in_sizes[1];                 // 2048
    const int V = in_sizes[0] / B;             // 32000

    cosarc_row_kernel<<<B, 256>>>(preds, labels, V);
    cosarc_final_kernel<<<1, 256>>>((float*)d_out, B);
}

// round 3
// speedup vs baseline: 1.0065x; 1.0065x over previous
#include <cuda_runtime.h>
#include <cuda_bf16.h>

#define MAX_ROWS 8192
__device__ double g_row_loss[MAX_ROWS];
__device__ unsigned int g_done = 0;   // self-resets each run -> graph-replay safe

__device__ __forceinline__ float ex2(float x) {
    float y;
    asm("ex2.approx.f32 %0, %1;" : "=f"(y) : "f"(x));
    return y;
}

// One block per row: sum exp(30*x) over the row, per-row epilogue, then the
// LAST block to finish reduces all row losses (deterministic fixed-order sum).
__global__ void __launch_bounds__(256) cosarc_fused_kernel(
    const float* __restrict__ preds,
    const int* __restrict__ labels,     // int32 (JAX x64 disabled)
    float* __restrict__ out,
    int V, int B)
{
    const int row = blockIdx.x;
    const float* rp = preds + (size_t)row * (size_t)V;
    const float4* p4 = reinterpret_cast<const float4*>(rp);
    const int n4 = V >> 2;
    const int stride = 256;

    // exp(30*x) = exp2(x * 30*log2(e))
    const float C = 30.0f * 1.4426950408889634f;

    float s0 = 0.f, s1 = 0.f, s2 = 0.f, s3 = 0.f;
    int i = threadIdx.x;

    // Main loop: 4 independent LDG.128 batched per iteration (MLP_p1 = 4),
    // 4 accumulators to break the FADD dependency chain.
    for (; i + 3 * stride < n4; i += 4 * stride) {
        float4 a = __ldg(&p4[i]);
        float4 b = __ldg(&p4[i + stride]);
        float4 c = __ldg(&p4[i + 2 * stride]);
        float4 d = __ldg(&p4[i + 3 * stride]);
        s0 += ex2(a.x * C) + ex2(a.y * C) + ex2(a.z * C) + ex2(a.w * C);
        s1 += ex2(b.x * C) + ex2(b.y * C) + ex2(b.z * C) + ex2(b.w * C);
        s2 += ex2(c.x * C) + ex2(c.y * C) + ex2(c.z * C) + ex2(c.w * C);
        s3 += ex2(d.x * C) + ex2(d.y * C) + ex2(d.z * C) + ex2(d.w * C);
    }
    for (; i < n4; i += stride) {
        float4 a = __ldg(&p4[i]);
        s0 += ex2(a.x * C) + ex2(a.y * C) + ex2(a.z * C) + ex2(a.w * C);
    }
    // Scalar tail (V % 4) — not hit for V=32000.
    for (int j = (n4 << 2) + threadIdx.x; j < V; j += stride)
        s0 += ex2(rp[j] * C);

    float s = (s0 + s1) + (s2 + s3);

    #pragma unroll
    for (int o = 16; o > 0; o >>= 1)
        s += __shfl_xor_sync(0xffffffffu, s, o);

    __shared__ float warpsum[8];
    const int wid = threadIdx.x >> 5;
    const int lid = threadIdx.x & 31;
    if (lid == 0) warpsum[wid] = s;
    __syncthreads();

    if (threadIdx.x == 0) {
        float tot = 0.f;
        #pragma unroll
        for (int w = 0; w < 8; w++) tot += warpsum[w];

        int lab = labels[row];
        if (lab < 0) lab = 0;
        if (lab >= V) lab = V - 1;
        const float target = rp[lab];

        double sum_others = (double)tot - (double)ex2(target * C);

        const double EPS = 1e-12;
        const double PI  = 3.14159265358979323846;
        double t = (double)target;
        t = fmin(fmax(t, -1.0 + EPS), 1.0 - EPS);
        double theta = acos(t);
        theta = fmin(fmax(theta, EPS), PI - EPS);
        double numerator = 30.0 * (cos(theta + 0.5) - 0.35);
        double denominator = exp(numerator) + sum_others;
        g_row_loss[row] = numerator - log(denominator);
    }

    // ---- last-block-done final reduction (threadFenceReduction pattern) ----
    __threadfence();
    __shared__ bool is_last;
    if (threadIdx.x == 0)
        is_last = (atomicAdd(&g_done, 1u) == (unsigned)(gridDim.x - 1));
    __syncthreads();

    if (is_last) {
        double d = 0.0;
        for (int j = threadIdx.x; j < B; j += stride)
            d += g_row_loss[j];

        #pragma unroll
        for (int o = 16; o > 0; o >>= 1)
            d += __shfl_xor_sync(0xffffffffu, d, o);

        __shared__ double dwarp[8];
        if (lid == 0) dwarp[wid] = d;
        __syncthreads();

        if (threadIdx.x == 0) {
            double tot = 0.0;
            #pragma unroll
            for (int w = 0; w < 8; w++) tot += dwarp[w];
            out[0] = (float)(-tot / (double)B);
            g_done = 0;   // reset for next graph replay
        }
    }
}

extern "C" void kernel_launch(void* const* d_in, const int* in_sizes, int n_in,
                              void* d_out, int out_size)
{
    const float* preds  = (const float*)d_in[0];
    const int*   labels = (const int*)d_in[1];

    const int B = in_sizes[1];                 // 2048
    const int V = in_sizes[0] / B;             // 32000

    cosarc_fused_kernel<<<B, 256>>>(preds, labels, (float*)d_out, V, B);
}